// round 8
// baseline (speedup 1.0000x reference)
#include <cuda_runtime.h>
#include <cstdint>

// AlignedLinear: y[n, o*9+d] = alpha * sum_i x[n, i*9+d] * K[r(d), i, o]
// r(d)=0 for d=0, 1 for d=1..3, 2 for d=4..8.
//
// R8: X staged into per-d SMEM planes [d][m][k] (k contiguous, row stride
// 132 -> ldmatrix conflict-free). A fragments via ONE ldmatrix.m8n8.x4 per
// (d,k8) instead of 4 LDS.32. K pre-converted (alpha folded, RNA tf32) to a
// fragment-major global buffer; B via coalesced LDG.64, double-buffered.
// Outputs overwrite dead plane columns (STS.64); one coalesced store at end.

#define MT        16
#define DIMT      9
#define MUL       128
#define ROWF      1152            // MUL*DIMT floats per node row
#define KR        132             // plane row stride (floats): 4 mod 32 banks
#define PLANE     (MT * KR)       // 2112 floats per d-plane
#define SMEM_W    (DIMT * PLANE)  // 19008 words = 76032 B
#define NTHREADS  128
#define ALPHA_F   0.08838834764831845f  // sqrt(1/128)

// kbuf[r][k8][nt][lane][j] : b_j for lane of fragment (k8, nt), irrep r
#define KB_WORDS  (3 * 16 * 16 * 64)
__device__ uint32_t g_kbuf[KB_WORDS];

static __device__ __forceinline__ uint32_t f2tf32(float f) {
    uint32_t u;
    asm("cvt.rna.tf32.f32 %0, %1;" : "=r"(u) : "f"(f));
    return u;
}

static __device__ __forceinline__ void mma_tf32(float c[4],
    uint32_t a0, uint32_t a1, uint32_t a2, uint32_t a3,
    uint32_t b0, uint32_t b1)
{
    asm volatile(
        "mma.sync.aligned.m16n8k8.row.col.f32.tf32.tf32.f32 "
        "{%0,%1,%2,%3}, {%4,%5,%6,%7}, {%8,%9}, {%0,%1,%2,%3};"
        : "+f"(c[0]), "+f"(c[1]), "+f"(c[2]), "+f"(c[3])
        : "r"(a0), "r"(a1), "r"(a2), "r"(a3), "r"(b0), "r"(b1));
}

// ---- Prep: K[r][i][o] fp32 -> fragment-major tf32 (RNA), alpha folded ----
__global__ void prep_k_kernel(const float* __restrict__ kern)
{
    int idx = blockIdx.x * blockDim.x + threadIdx.x;
    if (idx >= KB_WORDS) return;
    int j    = idx & 1;
    int lane = (idx >> 1) & 31;
    int nt   = (idx >> 6) & 15;
    int k8   = (idx >> 10) & 15;
    int r    = idx >> 14;
    int k = k8 * 8 + (lane & 3) + 4 * j;
    int o = nt * 8 + (lane >> 2);
    g_kbuf[idx] = f2tf32(ALPHA_F * kern[(r * MUL + k) * MUL + o]);
}

// One irrep group: GEMM all DC dims over k, A via ldmatrix from planes,
// then write C back into the now-dead plane columns o (STS.64 pairs).
template<int R, int D0, int DC, int KUNROLL>
static __device__ __forceinline__ void process_group(
    uint32_t* __restrict__ sPl, uint32_t lmat_base,
    int g, int tg, int lane, int wn)
{
    const uint2* kb = reinterpret_cast<const uint2*>(g_kbuf)
                    + ((size_t)R * 16 * 16 + (wn >> 3)) * 32 + lane;

    float c[DC][4][4];
    #pragma unroll
    for (int dd = 0; dd < DC; ++dd)
        #pragma unroll
        for (int nt = 0; nt < 4; ++nt)
            #pragma unroll
            for (int i = 0; i < 4; ++i) c[dd][nt][i] = 0.f;

    uint2 bcur[4];
    #pragma unroll
    for (int nt = 0; nt < 4; ++nt)
        bcur[nt] = __ldg(kb + nt * 32);

    #pragma unroll KUNROLL
    for (int k8 = 0; k8 < 16; ++k8) {
        uint2 bnxt[4];
        if (k8 < 15) {
            const uint2* kbn = kb + (k8 + 1) * (16 * 32);
            #pragma unroll
            for (int nt = 0; nt < 4; ++nt)
                bnxt[nt] = __ldg(kbn + nt * 32);
        }
        #pragma unroll
        for (int dd = 0; dd < DC; ++dd) {
            // One ldmatrix.x4 = full m16k8 A fragment for dim d = D0+dd.
            uint32_t addr = lmat_base
                          + (uint32_t)(((D0 + dd) * PLANE + k8 * 8) * 4);
            uint32_t a0, a1, a2, a3;
            asm volatile(
                "ldmatrix.sync.aligned.m8n8.x4.shared.b16 "
                "{%0,%1,%2,%3}, [%4];"
                : "=r"(a0), "=r"(a1), "=r"(a2), "=r"(a3) : "r"(addr));
            #pragma unroll
            for (int nt = 0; nt < 4; ++nt)
                mma_tf32(c[dd][nt], a0, a1, a2, a3, bcur[nt].x, bcur[nt].y);
        }
        #pragma unroll
        for (int nt = 0; nt < 4; ++nt) bcur[nt] = bnxt[nt];
    }

    __syncthreads();   // all warps done reading this group's planes

    // Overwrite dead plane columns with C: (o, o+1) contiguous -> STS.64.
    #pragma unroll
    for (int dd = 0; dd < DC; ++dd) {
        const int pb = (D0 + dd) * PLANE;
        #pragma unroll
        for (int nt = 0; nt < 4; ++nt) {
            int o = wn + nt * 8 + 2 * tg;
            uint2 vlo = make_uint2(__float_as_uint(c[dd][nt][0]),
                                   __float_as_uint(c[dd][nt][1]));
            uint2 vhi = make_uint2(__float_as_uint(c[dd][nt][2]),
                                   __float_as_uint(c[dd][nt][3]));
            *reinterpret_cast<uint2*>(sPl + pb + (g    ) * KR + o) = vlo;
            *reinterpret_cast<uint2*>(sPl + pb + (g + 8) * KR + o) = vhi;
        }
    }
}

__global__ void __launch_bounds__(NTHREADS, 3)
aligned_linear_tf32(const float* __restrict__ x,
                    float* __restrict__ y,
                    int n_nodes)
{
    extern __shared__ uint32_t sPl[];   // [DIMT][MT][KR] planes -> become Y

    const int tid  = threadIdx.x;
    const int lane = tid & 31;
    const int warp = tid >> 5;
    const int g    = lane >> 2;
    const int tg   = lane & 3;
    const int wn   = warp * 32;         // 4 warps x 32 output cols

    // ldmatrix row pointer for this lane: m = lane&15, +16B for k4..7 half.
    const uint32_t lmat_base =
        (uint32_t)__cvta_generic_to_shared(sPl)
        + (uint32_t)((((lane & 15) * KR) + ((lane >> 4) * 4)) * 4);

    const long long node0 = (long long)blockIdx.x * MT;
    const bool full_tile = (node0 + MT) <= (long long)n_nodes;

    // ---- Stage X: coalesced float4 gmem reads, de-interleave into planes ----
    #pragma unroll
    for (int it = tid; it < MT * (ROWF / 4); it += NTHREADS) {
        int row = it / (ROWF / 4);
        int c4  = it - row * (ROWF / 4);
        long long n = node0 + row;
        float4 v = make_float4(0.f, 0.f, 0.f, 0.f);
        if (full_tile || n < (long long)n_nodes)
            v = *reinterpret_cast<const float4*>(x + n * ROWF + c4 * 4);
        const int e0 = c4 * 4;
        const float vv[4] = {v.x, v.y, v.z, v.w};
        #pragma unroll
        for (int j = 0; j < 4; ++j) {
            int e = e0 + j;
            int k = e / DIMT;
            int d = e - k * DIMT;
            sPl[d * PLANE + row * KR + k] = f2tf32(vv[j]);
        }
    }
    __syncthreads();

    process_group<0, 0, 1, 2>(sPl, lmat_base, g, tg, lane, wn);
    process_group<1, 1, 3, 2>(sPl, lmat_base, g, tg, lane, wn);
    process_group<2, 4, 5, 1>(sPl, lmat_base, g, tg, lane, wn);

    __syncthreads();   // all writebacks visible

    // ---- Re-gather planes -> coalesced float4 store of the output tile ----
    #pragma unroll
    for (int it = tid; it < MT * (ROWF / 4); it += NTHREADS) {
        int row = it / (ROWF / 4);
        int c4  = it - row * (ROWF / 4);
        long long n = node0 + row;
        if (!full_tile && n >= (long long)n_nodes) continue;
        const int e0 = c4 * 4;
        float out[4];
        #pragma unroll
        for (int j = 0; j < 4; ++j) {
            int e = e0 + j;
            int k = e / DIMT;
            int d = e - k * DIMT;
            out[j] = __uint_as_float(sPl[d * PLANE + row * KR + k]);
        }
        float4 v = make_float4(out[0], out[1], out[2], out[3]);
        *reinterpret_cast<float4*>(y + n * ROWF + c4 * 4) = v;
    }
}

extern "C" void kernel_launch(void* const* d_in, const int* in_sizes, int n_in,
                              void* d_out, int out_size)
{
    const float* x = (const float*)d_in[0];
    const float* k = (const float*)d_in[1];
    float* y = (float*)d_out;
    int n_nodes = in_sizes[0] / ROWF;

    prep_k_kernel<<<(KB_WORDS + 255) / 256, 256>>>(k);

    size_t smem_bytes = (size_t)SMEM_W * sizeof(uint32_t);  // 76032 B
    cudaFuncSetAttribute(aligned_linear_tf32,
                         cudaFuncAttributeMaxDynamicSharedMemorySize,
                         (int)smem_bytes);

    int grid = (n_nodes + MT - 1) / MT;
    aligned_linear_tf32<<<grid, NTHREADS, smem_bytes>>>(x, y, n_nodes);
}

// round 9
// speedup vs baseline: 1.1070x; 1.1070x over previous
#include <cuda_runtime.h>
#include <cuda.h>
#include <cstdint>

// AlignedLinear: y[n, o*9+d] = alpha * sum_i x[n, i*9+d] * K[r(d), i, o]
// r(d)=0 for d=0, 1 for d=1..3, 2 for d=4..8.
//
// R9: TMA in / TMA out. X tile [16 nodes x 1152 floats] loaded by one
// cp.async.bulk.tensor.3d (box [32f, 16, 36], SW128) -> smem layout
// [seg][node][32f], swizzle key = node&7 (node stride = 1 chunk). A fragments
// via 4 LDS.32 with a per-lane constant XOR mask (conflict-free). Outputs
// overwrite the dead X words in the swizzled tile; one TMA store de-swizzles
// back to gmem. K pre-converted (alpha folded, RNA tf32) to fragment-major
// global buffer; B via coalesced LDG.64, double-buffered.

#define MT        16
#define DIMT      9
#define MUL       128
#define ROWF      1152
#define TILE_BYTES 73728        // 16 * 1152 * 4
#define NTHREADS  128
#define ALPHA_F   0.08838834764831845f  // sqrt(1/128)

#define KB_WORDS  (3 * 16 * 16 * 64)
__device__ __align__(16) uint32_t g_kbuf[KB_WORDS];

static __device__ __forceinline__ uint32_t f2tf32(float f) {
    uint32_t u;
    asm("cvt.rna.tf32.f32 %0, %1;" : "=r"(u) : "f"(f));
    return u;
}

static __device__ __forceinline__ void mma_tf32(float c[4],
    uint32_t a0, uint32_t a1, uint32_t a2, uint32_t a3,
    uint32_t b0, uint32_t b1)
{
    asm volatile(
        "mma.sync.aligned.m16n8k8.row.col.f32.tf32.tf32.f32 "
        "{%0,%1,%2,%3}, {%4,%5,%6,%7}, {%8,%9}, {%0,%1,%2,%3};"
        : "+f"(c[0]), "+f"(c[1]), "+f"(c[2]), "+f"(c[3])
        : "r"(a0), "r"(a1), "r"(a2), "r"(a3), "r"(b0), "r"(b1));
}

// ---- Prep: K[r][i][o] fp32 -> fragment-major tf32 (RNA), alpha folded ----
__global__ void prep_k_kernel(const float* __restrict__ kern)
{
    int idx = blockIdx.x * blockDim.x + threadIdx.x;
    if (idx >= KB_WORDS) return;
    int j    = idx & 1;
    int lane = (idx >> 1) & 31;
    int nt   = (idx >> 6) & 15;
    int k8   = (idx >> 10) & 15;
    int r    = idx >> 14;
    int k = k8 * 8 + (lane & 3) + 4 * j;
    int o = nt * 8 + (lane >> 2);
    g_kbuf[idx] = f2tf32(ALPHA_F * kern[(r * MUL + k) * MUL + o]);
}

// Swizzled byte offset of word w (= 9k+d within a node row) relative to the
// node's row base. Chunk = w>>5 (seg stride 16*128B in smem); in-chunk bytes
// XOR the per-lane mask ((node&7)<<4).
static __device__ __forceinline__ uint32_t swz(int w, uint32_t xm) {
    return (uint32_t)((w >> 5) * 2048) + ((((uint32_t)w & 31u) * 4u) ^ xm);
}

static __device__ __forceinline__ uint32_t lds32(uint32_t a) {
    uint32_t v;
    asm volatile("ld.shared.b32 %0, [%1];" : "=r"(v) : "r"(a));
    return v;
}
static __device__ __forceinline__ void sts32(uint32_t a, float v) {
    asm volatile("st.shared.b32 [%0], %1;" :: "r"(a), "f"(v));
}

template<int R, int D0, int DC, int KU>
static __device__ __forceinline__ void process_group(
    uint32_t tbase, int g, int tg, int lane, int warp)
{
    const uint2* kb = reinterpret_cast<const uint2*>(g_kbuf)
                    + ((size_t)R * 256 + warp * 4) * 32 + lane;
    const uint32_t xm   = (uint32_t)(g & 7) << 4;   // key(g) == key(g+8)
    const uint32_t rowb = tbase + (uint32_t)g * 128u;

    float c[DC][4][4];
    #pragma unroll
    for (int dd = 0; dd < DC; ++dd)
        #pragma unroll
        for (int nt = 0; nt < 4; ++nt)
            #pragma unroll
            for (int i = 0; i < 4; ++i) c[dd][nt][i] = 0.f;

    uint2 bcur[4];
    #pragma unroll
    for (int nt = 0; nt < 4; ++nt)
        bcur[nt] = __ldg(kb + nt * 32);

    #pragma unroll KU
    for (int k8 = 0; k8 < 16; ++k8) {
        uint2 bnxt[4];
        if (k8 < 15) {
            const uint2* kbn = kb + (k8 + 1) * 512;
            #pragma unroll
            for (int nt = 0; nt < 4; ++nt)
                bnxt[nt] = __ldg(kbn + nt * 32);
        }
        #pragma unroll
        for (int dd = 0; dd < DC; ++dd) {
            const int w0 = 72 * k8 + 9 * tg + (D0 + dd);
            const uint32_t o0 = rowb + swz(w0,      xm);
            const uint32_t o1 = rowb + swz(w0 + 36, xm);
            uint32_t a0 = lds32(o0);
            uint32_t a1 = lds32(o0 + 1024);   // row g+8, same key
            uint32_t a2 = lds32(o1);
            uint32_t a3 = lds32(o1 + 1024);
            #pragma unroll
            for (int nt = 0; nt < 4; ++nt)
                mma_tf32(c[dd][nt], a0, a1, a2, a3, bcur[nt].x, bcur[nt].y);
        }
        #pragma unroll
        for (int nt = 0; nt < 4; ++nt) bcur[nt] = bnxt[nt];
    }

    __syncthreads();   // all warps done reading this group's X words

    // Overwrite the dead words (o*9+d of this group) in the swizzled tile.
    #pragma unroll
    for (int dd = 0; dd < DC; ++dd) {
        #pragma unroll
        for (int nt = 0; nt < 4; ++nt) {
            const int o = warp * 32 + nt * 8 + 2 * tg;
            const int w = o * 9 + (D0 + dd);
            sts32(rowb        + swz(w,     xm), c[dd][nt][0]);
            sts32(rowb        + swz(w + 9, xm), c[dd][nt][1]);
            sts32(rowb + 1024 + swz(w,     xm), c[dd][nt][2]);
            sts32(rowb + 1024 + swz(w + 9, xm), c[dd][nt][3]);
        }
    }
}

__global__ void __launch_bounds__(NTHREADS, 3)
aligned_linear_tma(const __grid_constant__ CUtensorMap tmx,
                   const __grid_constant__ CUtensorMap tmy)
{
    extern __shared__ uint32_t dyn[];
    const uint32_t raw   = (uint32_t)__cvta_generic_to_shared(dyn);
    const uint32_t tbase = (raw + 1023u) & ~1023u;   // SW128 needs 1KB align
    const uint32_t bar   = tbase + TILE_BYTES;       // mbarrier after tile

    const int tid  = threadIdx.x;
    const int lane = tid & 31;
    const int warp = tid >> 5;
    const int g    = lane >> 2;
    const int tg   = lane & 3;
    const int node0 = blockIdx.x * MT;

    if (tid == 0)
        asm volatile("mbarrier.init.shared.b64 [%0], 1;" :: "r"(bar));
    __syncthreads();

    if (tid == 0) {
        asm volatile("mbarrier.arrive.expect_tx.shared.b64 _, [%0], %1;"
                     :: "r"(bar), "r"(TILE_BYTES));
        asm volatile(
            "cp.async.bulk.tensor.3d.shared::cta.global.tile"
            ".mbarrier::complete_tx::bytes [%0], [%1, {%2, %3, %4}], [%5];"
            :: "r"(tbase), "l"(&tmx),
               "r"(0), "r"(node0), "r"(0), "r"(bar) : "memory");
    }
    // Wait for the tile (parity 0).
    asm volatile(
        "{\n\t.reg .pred P;\n\t"
        "WL_%=:\n\t"
        "mbarrier.try_wait.parity.acquire.cta.shared::cta.b64 P, [%0], %1, 0x989680;\n\t"
        "@P bra WD_%=;\n\t"
        "bra WL_%=;\n\t"
        "WD_%=:\n\t}"
        :: "r"(bar), "r"(0u) : "memory");

    process_group<0, 0, 1, 2>(tbase, g, tg, lane, warp);
    process_group<1, 1, 3, 1>(tbase, g, tg, lane, warp);
    process_group<2, 4, 5, 1>(tbase, g, tg, lane, warp);

    __syncthreads();   // all writebacks visible

    if (tid == 0) {
        asm volatile("fence.proxy.async;" ::: "memory");
        asm volatile(
            "cp.async.bulk.tensor.3d.global.shared::cta.tile.bulk_group "
            "[%0, {%1, %2, %3}], [%4];"
            :: "l"(&tmy), "r"(0), "r"(node0), "r"(0), "r"(tbase) : "memory");
        asm volatile("cp.async.bulk.commit_group;");
        asm volatile("cp.async.bulk.wait_group 0;");
    }
}

extern "C" void kernel_launch(void* const* d_in, const int* in_sizes, int n_in,
                              void* d_out, int out_size)
{
    const float* x = (const float*)d_in[0];
    const float* k = (const float*)d_in[1];
    float* y = (float*)d_out;
    int n_nodes = in_sizes[0] / ROWF;

    prep_k_kernel<<<(KB_WORDS + 255) / 256, 256>>>(k);

    // Driver entry point (no -lcuda needed).
    typedef CUresult (*enc_t)(CUtensorMap*, CUtensorMapDataType, cuuint32_t,
                              void*, const cuuint64_t*, const cuuint64_t*,
                              const cuuint32_t*, const cuuint32_t*,
                              CUtensorMapInterleave, CUtensorMapSwizzle,
                              CUtensorMapL2promotion, CUtensorMapFloatOOBfill);
    enc_t enc = nullptr;
    {
        void* p = nullptr;
        cudaDriverEntryPointQueryResult qr;
        cudaGetDriverEntryPointByVersion("cuTensorMapEncodeTiled", &p, 12000,
                                         cudaEnableDefault, &qr);
        enc = (enc_t)p;
    }

    // View: [32 floats][node][36 segs]; box [32, 16, 36]; SW128.
    cuuint64_t dims[3]    = {32, (cuuint64_t)n_nodes, 36};
    cuuint64_t strides[2] = {(cuuint64_t)ROWF * 4, 128};
    cuuint32_t box[3]     = {32, MT, 36};
    cuuint32_t es[3]      = {1, 1, 1};

    CUtensorMap tmx, tmy;
    enc(&tmx, CU_TENSOR_MAP_DATA_TYPE_FLOAT32, 3, (void*)x,
        dims, strides, box, es,
        CU_TENSOR_MAP_INTERLEAVE_NONE, CU_TENSOR_MAP_SWIZZLE_128B,
        CU_TENSOR_MAP_L2_PROMOTION_L2_128B, CU_TENSOR_MAP_FLOAT_OOB_FILL_NONE);
    enc(&tmy, CU_TENSOR_MAP_DATA_TYPE_FLOAT32, 3, (void*)y,
        dims, strides, box, es,
        CU_TENSOR_MAP_INTERLEAVE_NONE, CU_TENSOR_MAP_SWIZZLE_128B,
        CU_TENSOR_MAP_L2_PROMOTION_L2_128B, CU_TENSOR_MAP_FLOAT_OOB_FILL_NONE);

    size_t smem = TILE_BYTES + 1024 + 16;   // align slack + mbarrier
    cudaFuncSetAttribute(aligned_linear_tma,
                         cudaFuncAttributeMaxDynamicSharedMemorySize,
                         (int)smem);

    int grid = (n_nodes + MT - 1) / MT;
    aligned_linear_tma<<<grid, NTHREADS, smem>>>(tmx, tmy);
}